// round 5
// baseline (speedup 1.0000x reference)
#include <cuda_runtime.h>

#define NPTS 4096
#define NW 128          // 4096/32 words per conflict row
#define NPROB 4         // (b, class) pairs: 2 batches x 2 classes
#define ACAP 2048       // shared alive-list capacity (realistic A << this)

static __device__ float4   g_pos_u[NPROB][NPTS];        // unsorted positions (z,y,x,-)
static __device__ float4   g_pos_s[NPROB][NPTS];        // sorted positions   (z,y,x,aa)
static __device__ float4   g_alist[NPROB][NPTS];        // overflow alive list (rarely used)
static __device__ unsigned g_conflict[NPROB][NPTS * NW];// predecessor-conflict bitmask rows
static __device__ int      g_M[NPROB];                  // valid count per problem

// XLA expands logistic(x) = 0.5 + 0.5*tanh(0.5*x); tanh uses Eigen's rational approx.
__device__ __forceinline__ float xla_logistic(float x) {
    float t  = 0.5f * x;
    float ax = fabsf(t);
    float xc = fminf(fmaxf(t, -7.90531110763549805f), 7.90531110763549805f);
    float x2 = xc * xc;
    float p = fmaf(x2, -2.76076847742355e-16f, 2.00018790482477e-13f);
    p = fmaf(x2, p, -8.60467152213735e-11f);
    p = fmaf(x2, p,  5.12229709037114e-08f);
    p = fmaf(x2, p,  1.48572235717979e-05f);
    p = fmaf(x2, p,  6.37261928875436e-04f);
    p = fmaf(x2, p,  4.89352455891786e-03f);
    p = xc * p;
    float q = fmaf(x2, 1.19825839466702e-06f, 1.18534705686654e-04f);
    q = fmaf(x2, q, 2.26843463243900e-03f);
    q = fmaf(x2, q, 4.89352518554385e-03f);
    float y = p / q;
    if (ax < 0.0004f) y = t;
    return __fadd_rn(__fmul_rn(0.5f, y), 0.5f);
}

// ---------------------------------------------------------------------------
// Kernel 1: prep (conf/argmax, positions), compact valid, bitonic-sort only
// the valid subset (padded to next pow2). Invalid entries never matter.
// ---------------------------------------------------------------------------
__global__ __launch_bounds__(1024, 1) void k_prep_sort(
    const float* __restrict__ pred_clses,
    const float* __restrict__ pred_boxes)
{
    __shared__ unsigned long long skey[NPTS];   // 32 KB
    __shared__ int sM;

    int prob = blockIdx.x;
    int b    = prob >> 1;
    int cls  = (prob & 1) + 1;
    int tid  = threadIdx.x;

    if (tid == 0) sM = 0;
    __syncthreads();

    for (int n = tid; n < NPTS; n += 1024) {
        float cv0 = pred_clses[(b * 3 + 0) * NPTS + n];
        float cv1 = pred_clses[(b * 3 + 1) * NPTS + n];
        float cv2 = pred_clses[(b * 3 + 2) * NPTS + n];
        float conf = cv0; int arg = 0;
        if (cv1 > conf) { conf = cv1; arg = 1; }
        if (cv2 > conf) { conf = cv2; arg = 2; }
        if (arg == cls) {
            // descending conf, ascending index tiebreak -> ascending 64-bit key
            unsigned cb  = __float_as_uint(conf);
            unsigned ord = cb ^ ((cb & 0x80000000u) ? 0xFFFFFFFFu : 0x80000000u);
            int slot = atomicAdd(&sM, 1);
            skey[slot] = (((unsigned long long)(~ord)) << 32) | (unsigned)n;
        }
        int d = n >> 10, h = (n >> 5) & 31, w = n & 31;
        float bz = pred_boxes[(b * 3 + 0) * NPTS + n];
        float by = pred_boxes[(b * 3 + 1) * NPTS + n];
        float bx = pred_boxes[(b * 3 + 2) * NPTS + n];
        float sz = xla_logistic(bz);
        float sy = xla_logistic(by);
        float sx = xla_logistic(bx);
        float pz = __fmul_rn(__fdiv_rn(__fadd_rn((float)d, sz),  4.0f),  3.0f);
        float py = __fmul_rn(__fdiv_rn(__fadd_rn((float)h, sy), 32.0f), 25.0f);
        float px = __fmul_rn(__fdiv_rn(__fadd_rn((float)w, sx), 32.0f), 25.0f);
        g_pos_u[prob][n] = make_float4(pz, py, px, 0.0f);
    }
    __syncthreads();

    int M = sM;
    int P = 1;
    while (P < M) P <<= 1;            // next pow2 >= M
    if (P < 2) P = 2;

    for (int s = M + tid; s < P; s += 1024)
        skey[s] = 0xFFFFFFFFFFFFFFFFull;
    __syncthreads();

    // bitonic sort, ascending, P elements
    for (int k = 2; k <= P; k <<= 1) {
        for (int j = k >> 1; j > 0; j >>= 1) {
            for (int i = tid; i < P; i += 1024) {
                int ixj = i ^ j;
                if (ixj > i) {
                    unsigned long long a = skey[i], c = skey[ixj];
                    bool up = ((i & k) == 0);
                    if (up ? (a > c) : (a < c)) { skey[i] = c; skey[ixj] = a; }
                }
            }
            __syncthreads();
        }
    }

    // gather sorted positions + precompute aa = z^2 + y^2 + x^2 (left-assoc)
    for (int s = tid; s < M; s += 1024) {
        int idx = (int)(skey[s] & 0xFFFFFFFFu);
        float4 p = g_pos_u[prob][idx];
        p.w = __fadd_rn(__fadd_rn(__fmul_rn(p.x, p.x), __fmul_rn(p.y, p.y)),
                        __fmul_rn(p.z, p.z));
        g_pos_s[prob][s] = p;
    }
    if (tid == 0) g_M[prob] = M;
}

// ---------------------------------------------------------------------------
// Kernel 2: conflict bitmask build — warp per row j, ballot assembles words
// ---------------------------------------------------------------------------
__global__ __launch_bounds__(256) void k_conflict()
{
    int prob = blockIdx.y;
    int M    = g_M[prob];
    float c2 = (prob & 1) ? 0.5625f : 1.0f;   // cutoff^2 (0.75^2, 1.0^2)
    int lane = threadIdx.x & 31;
    int gw   = blockIdx.x * (blockDim.x >> 5) + (threadIdx.x >> 5);
    int nwarps = gridDim.x * (blockDim.x >> 5);
    const float4* pos = g_pos_s[prob];
    unsigned* cf = g_conflict[prob];

    for (int j = gw + 1; j < M; j += nwarps) {
        float4 pj = pos[j];
        int wend = (j - 1) >> 5;
        for (int w = 0; w <= wend; w++) {
            int i = (w << 5) + lane;
            bool hit = false;
            if (i < j) {
                float4 pi = pos[i];
                float dot = __fadd_rn(__fadd_rn(__fmul_rn(pi.x, pj.x),
                                                __fmul_rn(pi.y, pj.y)),
                                      __fmul_rn(pi.z, pj.z));
                float dist = __fsub_rn(__fadd_rn(pi.w, pj.w), __fmul_rn(2.0f, dot));
                hit = dist < c2;
            }
            unsigned bits = __ballot_sync(0xFFFFFFFFu, hit);
            if (lane == 0) cf[(size_t)j * NW + w] = bits;
        }
    }
}

// ---------------------------------------------------------------------------
// Kernel 3 (fused): NMS iterations (warp-per-row, coalesced word scan) +
// survivor compaction into shared + target matching + output write.
// One block per problem; block writes its own 3 outputs.
// ---------------------------------------------------------------------------
__global__ __launch_bounds__(1024, 1) void k_nms_match(
    const int*   __restrict__ targ_clses,
    const float* __restrict__ targ_boxes,
    float*       __restrict__ out)
{
    __shared__ unsigned alive[NW], Fb[NW], NA[NW];
    __shared__ int sChanged, sCount, sLP, sLT, sTP;
    __shared__ float4 s_al[ACAP];     // 32 KB compacted survivors

    int prob = blockIdx.x;
    int b    = prob >> 1;
    int cls  = (prob & 1) + 1;
    float c2 = (prob & 1) ? 0.5625f : 1.0f;
    const float HI = (float)(3.0 + 1e-05);
    int tid  = threadIdx.x;
    int warp = tid >> 5, lane = tid & 31;
    int M    = g_M[prob];

    if (tid < NW) {
        int fullw = M >> 5, rem = M & 31;
        unsigned v = 0;
        if (tid < fullw) v = 0xFFFFFFFFu;
        else if (tid == fullw && rem) v = (1u << rem) - 1u;
        alive[tid] = v;
    }
    if (tid == 0) { sCount = 0; sLP = 0; sLT = 0; sTP = 0; }
    __syncthreads();

    const unsigned* cf = g_conflict[prob];

    for (int it = 0; it < 32; it++) {
        // pass 1: F = alive minus rows with an alive conflicting predecessor
        if (tid < NW) Fb[tid] = alive[tid];
        if (tid == 0) sChanged = 0;
        __syncthreads();
        for (int s = warp; s < M; s += 32) {
            if (!((alive[s >> 5] >> (s & 31)) & 1)) continue;   // warp-uniform
            bool hit = false;
            int wend = (s - 1) >> 5;              // s==0 -> -1, loop skipped
            const unsigned* row = cf + (size_t)s * NW;
            for (int w = lane; w <= wend; w += 32) {
                unsigned aw = alive[w];
                if (aw) hit |= (row[w] & aw) != 0;
            }
            if (__ballot_sync(0xFFFFFFFFu, hit)) {
                if (lane == 0) atomicAnd(&Fb[s >> 5], ~(1u << (s & 31)));
            }
        }
        __syncthreads();
        // pass 2: alive &= no conflicting predecessor in F
        if (tid < NW) NA[tid] = alive[tid];
        __syncthreads();
        for (int s = warp; s < M; s += 32) {
            if (!((alive[s >> 5] >> (s & 31)) & 1)) continue;
            bool hit = false;
            int wend = (s - 1) >> 5;
            const unsigned* row = cf + (size_t)s * NW;
            for (int w = lane; w <= wend; w += 32) {
                unsigned fw = Fb[w];
                if (fw) hit |= (row[w] & fw) != 0;
            }
            if (__ballot_sync(0xFFFFFFFFu, hit)) {
                if (lane == 0) atomicAnd(&NA[s >> 5], ~(1u << (s & 31)));
            }
        }
        __syncthreads();
        if (tid < NW) {
            if (NA[tid] != alive[tid]) sChanged = 1;
            alive[tid] = NA[tid];
        }
        __syncthreads();
        int stop = (sChanged == 0);   // fixed point => later iters identical
        __syncthreads();
        if (stop) break;
    }

    // compact survivors into shared (order irrelevant); count lp
    for (int s = tid; s < M; s += 1024) {
        if ((alive[s >> 5] >> (s & 31)) & 1) {
            float4 p = g_pos_s[prob][s];
            int id = atomicAdd(&sCount, 1);
            if (id < ACAP) s_al[id] = p;
            else           g_alist[prob][id] = p;   // overflow slot id (< NPTS)
            if (p.x >= 0.0f && p.x < HI) atomicAdd(&sLP, 1);
        }
    }
    __syncthreads();

    int A  = sCount;
    int Ak = A < ACAP ? A : ACAP;

    // match targets against shared alive list (chunked, MLP-8)
    int ltc = 0, tpc = 0;
    for (int n = tid; n < NPTS; n += 1024) {
        if (targ_clses[b * NPTS + n] != cls) continue;
        int d = n >> 10, h = (n >> 5) & 31, w = n & 31;
        float t0 = targ_boxes[(b * NPTS + n) * 3 + 0];
        float t1 = targ_boxes[(b * NPTS + n) * 3 + 1];
        float t2 = targ_boxes[(b * NPTS + n) * 3 + 2];
        float tz = __fmul_rn(__fdiv_rn(__fadd_rn((float)d, t0),  4.0f),  3.0f);
        float ty = __fmul_rn(__fdiv_rn(__fadd_rn((float)h, t1), 32.0f), 25.0f);
        float tx = __fmul_rn(__fdiv_rn(__fadd_rn((float)w, t2), 32.0f), 25.0f);
        if (!(tz >= 0.0f && tz < HI)) continue;
        ltc++;
        float bb = __fadd_rn(__fadd_rn(__fmul_rn(tz, tz), __fmul_rn(ty, ty)),
                             __fmul_rn(tx, tx));
        bool found = false;
        for (int a0 = 0; a0 < Ak && !found; a0 += 8) {
            bool hit = false;
            #pragma unroll
            for (int k = 0; k < 8; k++) {
                int a = a0 + k;
                if (a < Ak) {
                    float4 p = s_al[a];
                    float dot = __fadd_rn(__fadd_rn(__fmul_rn(p.x, tz),
                                                    __fmul_rn(p.y, ty)),
                                          __fmul_rn(p.z, tx));
                    float dist = __fsub_rn(__fadd_rn(p.w, bb), __fmul_rn(2.0f, dot));
                    hit |= (dist < c2);
                }
            }
            found = hit;
        }
        for (int a = ACAP; a < A && !found; a++) {   // overflow fallback
            float4 p = g_alist[prob][a];
            float dot = __fadd_rn(__fadd_rn(__fmul_rn(p.x, tz),
                                            __fmul_rn(p.y, ty)),
                                  __fmul_rn(p.z, tx));
            float dist = __fsub_rn(__fadd_rn(p.w, bb), __fmul_rn(2.0f, dot));
            found = dist < c2;
        }
        if (found) tpc++;
    }
    // warp-reduce then shared-atomic
    ltc = __reduce_add_sync(0xFFFFFFFFu, ltc);
    tpc = __reduce_add_sync(0xFFFFFFFFu, tpc);
    if (lane == 0) {
        if (ltc) atomicAdd(&sLT, ltc);
        if (tpc) atomicAdd(&sTP, tpc);
    }
    __syncthreads();

    if (tid == 0) {
        int tp = sTP, lp = sLP, lt = sLT;
        out[prob * 3 + 0] = (float)tp;
        out[prob * 3 + 1] = (float)(lp - tp);
        out[prob * 3 + 2] = (float)(lt - tp);
    }
}

extern "C" void kernel_launch(void* const* d_in, const int* in_sizes, int n_in,
                              void* d_out, int out_size)
{
    const float* pred_clses = (const float*)d_in[0];
    const float* pred_boxes = (const float*)d_in[1];
    const int*   targ_clses = (const int*)d_in[2];
    const float* targ_boxes = (const float*)d_in[3];
    float* out = (float*)d_out;

    k_prep_sort<<<NPROB, 1024>>>(pred_clses, pred_boxes);
    k_conflict<<<dim3(32, NPROB), 256>>>();
    k_nms_match<<<NPROB, 1024>>>(targ_clses, targ_boxes, out);
}

// round 6
// speedup vs baseline: 1.3486x; 1.3486x over previous
#include <cuda_runtime.h>

#define NPTS 4096
#define NW 128            // max bitset words (4096/32)
#define NPROB 4           // (b, class) pairs
#define ACAP 2048         // shared alive-list capacity
#define EMAX (1 << 20)    // edge capacity per problem (expected ~2K)

static __device__ float4             g_pt[NPROB][NPTS];   // compacted valid pts (z,y,x,aa)
static __device__ unsigned long long g_key[NPROB][NPTS];  // order key (asc = higher priority)
static __device__ unsigned           g_edges[NPROB][EMAX];// (succ<<12)|pred
static __device__ int                g_ecnt[NPROB];
static __device__ int                g_M[NPROB];
static __device__ float4             g_aovf[NPROB][NPTS]; // alive-list overflow (unlikely)

// XLA logistic(x) = 0.5 + 0.5*tanh(0.5x), Eigen rational tanh
__device__ __forceinline__ float xla_logistic(float x) {
    float t  = 0.5f * x;
    float ax = fabsf(t);
    float xc = fminf(fmaxf(t, -7.90531110763549805f), 7.90531110763549805f);
    float x2 = xc * xc;
    float p = fmaf(x2, -2.76076847742355e-16f, 2.00018790482477e-13f);
    p = fmaf(x2, p, -8.60467152213735e-11f);
    p = fmaf(x2, p,  5.12229709037114e-08f);
    p = fmaf(x2, p,  1.48572235717979e-05f);
    p = fmaf(x2, p,  6.37261928875436e-04f);
    p = fmaf(x2, p,  4.89352455891786e-03f);
    p = xc * p;
    float q = fmaf(x2, 1.19825839466702e-06f, 1.18534705686654e-04f);
    q = fmaf(x2, q, 2.26843463243900e-03f);
    q = fmaf(x2, q, 4.89352518554385e-03f);
    float y = p / q;
    if (ax < 0.0004f) y = t;
    return __fadd_rn(__fmul_rn(0.5f, y), 0.5f);
}

// ---------------------------------------------------------------------------
// Kernel 1: compute conf/argmax; compact valid points with positions + keys.
// No sort needed — NMS direction comes from key comparison.
// ---------------------------------------------------------------------------
__global__ __launch_bounds__(1024, 1) void k_prep(
    const float* __restrict__ pred_clses,
    const float* __restrict__ pred_boxes)
{
    __shared__ int sM;
    int prob = blockIdx.x;
    int b    = prob >> 1;
    int cls  = (prob & 1) + 1;
    int tid  = threadIdx.x;

    if (tid == 0) { sM = 0; g_ecnt[prob] = 0; }
    __syncthreads();

    for (int n = tid; n < NPTS; n += 1024) {
        float cv0 = pred_clses[(b * 3 + 0) * NPTS + n];
        float cv1 = pred_clses[(b * 3 + 1) * NPTS + n];
        float cv2 = pred_clses[(b * 3 + 2) * NPTS + n];
        float conf = cv0; int arg = 0;
        if (cv1 > conf) { conf = cv1; arg = 1; }
        if (cv2 > conf) { conf = cv2; arg = 2; }
        if (arg != cls) continue;

        int d = n >> 10, h = (n >> 5) & 31, w = n & 31;
        float sz = xla_logistic(pred_boxes[(b * 3 + 0) * NPTS + n]);
        float sy = xla_logistic(pred_boxes[(b * 3 + 1) * NPTS + n]);
        float sx = xla_logistic(pred_boxes[(b * 3 + 2) * NPTS + n]);
        float pz = __fmul_rn(__fdiv_rn(__fadd_rn((float)d, sz),  4.0f),  3.0f);
        float py = __fmul_rn(__fdiv_rn(__fadd_rn((float)h, sy), 32.0f), 25.0f);
        float px = __fmul_rn(__fdiv_rn(__fadd_rn((float)w, sx), 32.0f), 25.0f);
        float aa = __fadd_rn(__fadd_rn(__fmul_rn(pz, pz), __fmul_rn(py, py)),
                             __fmul_rn(px, px));

        // ascending key == (conf desc, index asc)
        unsigned cb  = __float_as_uint(conf);
        unsigned ord = cb ^ ((cb & 0x80000000u) ? 0xFFFFFFFFu : 0x80000000u);
        unsigned long long key = (((unsigned long long)(~ord)) << 32) | (unsigned)n;

        int slot = atomicAdd(&sM, 1);
        g_pt[prob][slot]  = make_float4(pz, py, px, aa);
        g_key[prob][slot] = key;
    }
    __syncthreads();
    if (tid == 0) g_M[prob] = sM;
}

// ---------------------------------------------------------------------------
// Kernel 2: sparse conflict edges. Warp per row j, lanes over i<j (array
// order), emit directed edge (succ<<12 | pred) by key order, ballot-aggregated.
// ---------------------------------------------------------------------------
__global__ __launch_bounds__(256) void k_edges()
{
    int prob = blockIdx.y;
    int M    = g_M[prob];
    float c2 = (prob & 1) ? 0.5625f : 1.0f;
    int lane = threadIdx.x & 31;
    int gw   = blockIdx.x * (blockDim.x >> 5) + (threadIdx.x >> 5);
    int nwarps = gridDim.x * (blockDim.x >> 5);
    const float4* __restrict__ pt = g_pt[prob];
    const unsigned long long* __restrict__ key = g_key[prob];

    for (int j = gw + 1; j < M; j += nwarps) {
        float4 pj = pt[j];
        unsigned long long kj = key[j];
        for (int i0 = 0; i0 < j; i0 += 32) {
            int i = i0 + lane;
            bool hit = false;
            if (i < j) {
                float4 pi = pt[i];
                float dot = __fadd_rn(__fadd_rn(__fmul_rn(pi.x, pj.x),
                                                __fmul_rn(pi.y, pj.y)),
                                      __fmul_rn(pi.z, pj.z));
                float dist = __fsub_rn(__fadd_rn(pi.w, pj.w), __fmul_rn(2.0f, dot));
                hit = dist < c2;
            }
            unsigned mask = __ballot_sync(0xFFFFFFFFu, hit);
            if (mask) {
                int leader = __ffs(mask) - 1;
                int base = 0;
                if (lane == leader) base = atomicAdd(&g_ecnt[prob], __popc(mask));
                base = __shfl_sync(0xFFFFFFFFu, base, leader);
                if (hit) {
                    int idx = base + __popc(mask & ((1u << lane) - 1u));
                    if (idx < EMAX) {
                        unsigned pred, succ;
                        if (key[i] < kj) { pred = (unsigned)i; succ = (unsigned)j; }
                        else             { pred = (unsigned)j; succ = (unsigned)i; }
                        g_edges[prob][idx] = (succ << 12) | pred;
                    }
                }
            }
        }
    }
}

// ---------------------------------------------------------------------------
// Kernel 3: NMS on sparse edges (thread-per-edge, shared bitsets) + survivor
// compaction to shared + target matching + output. One block per problem.
// ---------------------------------------------------------------------------
__global__ __launch_bounds__(1024, 1) void k_nms_match(
    const int*   __restrict__ targ_clses,
    const float* __restrict__ targ_boxes,
    float*       __restrict__ out)
{
    __shared__ unsigned alive[NW], Fb[NW], bF[NW], bA[NW];
    __shared__ int sChanged, sCount, sLP, sLT, sTP;
    __shared__ float4 s_al[ACAP];

    int prob = blockIdx.x;
    int b    = prob >> 1;
    int cls  = (prob & 1) + 1;
    float c2 = (prob & 1) ? 0.5625f : 1.0f;
    const float HI = (float)(3.0 + 1e-05);
    int tid  = threadIdx.x;
    int lane = tid & 31;
    int M    = g_M[prob];
    int E    = g_ecnt[prob]; if (E > EMAX) E = EMAX;

    if (tid < NW) {
        int fullw = M >> 5, rem = M & 31;
        unsigned v = 0;
        if (tid < fullw) v = 0xFFFFFFFFu;
        else if (tid == fullw && rem) v = (1u << rem) - 1u;
        alive[tid] = v;
    }
    if (tid == 0) { sCount = 0; sLP = 0; sLT = 0; sTP = 0; }
    __syncthreads();

    const unsigned* __restrict__ ed = g_edges[prob];

    for (int it = 0; it < 32; it++) {
        if (tid < NW) bF[tid] = 0;
        if (tid == 0) sChanged = 0;
        __syncthreads();
        // pass 1: bF[s] |= alive[p]   ->  F = alive & ~bF
        for (int e = tid; e < E; e += 1024) {
            unsigned w = ed[e];
            int p = w & 0xFFF, s = w >> 12;
            if ((alive[p >> 5] >> (p & 31)) & 1)
                atomicOr(&bF[s >> 5], 1u << (s & 31));
        }
        __syncthreads();
        if (tid < NW) { Fb[tid] = alive[tid] & ~bF[tid]; bA[tid] = 0; }
        __syncthreads();
        // pass 2: bA[s] |= F[p]  ->  alive &= ~bA
        for (int e = tid; e < E; e += 1024) {
            unsigned w = ed[e];
            int p = w & 0xFFF, s = w >> 12;
            if ((Fb[p >> 5] >> (p & 31)) & 1)
                atomicOr(&bA[s >> 5], 1u << (s & 31));
        }
        __syncthreads();
        if (tid < NW) {
            unsigned na = alive[tid] & ~bA[tid];
            if (na != alive[tid]) sChanged = 1;
            alive[tid] = na;
        }
        __syncthreads();
        int stop = (sChanged == 0);   // fixed point => later iters identical
        __syncthreads();
        if (stop) break;
    }

    // compact survivors into shared; count lp (z in [0, HI))
    for (int s = tid; s < M; s += 1024) {
        if ((alive[s >> 5] >> (s & 31)) & 1) {
            float4 p = g_pt[prob][s];
            int id = atomicAdd(&sCount, 1);
            if (id < ACAP) s_al[id] = p;
            else           g_aovf[prob][id] = p;
            if (p.x >= 0.0f && p.x < HI) atomicAdd(&sLP, 1);
        }
    }
    __syncthreads();

    int A  = sCount;
    int Ak = A < ACAP ? A : ACAP;

    // match targets against shared alive list (8-way unrolled)
    int ltc = 0, tpc = 0;
    for (int n = tid; n < NPTS; n += 1024) {
        if (targ_clses[b * NPTS + n] != cls) continue;
        int d = n >> 10, h = (n >> 5) & 31, w = n & 31;
        float t0 = targ_boxes[(b * NPTS + n) * 3 + 0];
        float t1 = targ_boxes[(b * NPTS + n) * 3 + 1];
        float t2 = targ_boxes[(b * NPTS + n) * 3 + 2];
        float tz = __fmul_rn(__fdiv_rn(__fadd_rn((float)d, t0),  4.0f),  3.0f);
        float ty = __fmul_rn(__fdiv_rn(__fadd_rn((float)h, t1), 32.0f), 25.0f);
        float tx = __fmul_rn(__fdiv_rn(__fadd_rn((float)w, t2), 32.0f), 25.0f);
        if (!(tz >= 0.0f && tz < HI)) continue;
        ltc++;
        float bb = __fadd_rn(__fadd_rn(__fmul_rn(tz, tz), __fmul_rn(ty, ty)),
                             __fmul_rn(tx, tx));
        bool found = false;
        for (int a0 = 0; a0 < Ak && !found; a0 += 8) {
            bool hit = false;
            #pragma unroll
            for (int k = 0; k < 8; k++) {
                int a = a0 + k;
                if (a < Ak) {
                    float4 p = s_al[a];
                    float dot = __fadd_rn(__fadd_rn(__fmul_rn(p.x, tz),
                                                    __fmul_rn(p.y, ty)),
                                          __fmul_rn(p.z, tx));
                    float dist = __fsub_rn(__fadd_rn(p.w, bb), __fmul_rn(2.0f, dot));
                    hit |= (dist < c2);
                }
            }
            found = hit;
        }
        for (int a = ACAP; a < A && !found; a++) {   // overflow fallback
            float4 p = g_aovf[prob][a];
            float dot = __fadd_rn(__fadd_rn(__fmul_rn(p.x, tz),
                                            __fmul_rn(p.y, ty)),
                                  __fmul_rn(p.z, tx));
            float dist = __fsub_rn(__fadd_rn(p.w, bb), __fmul_rn(2.0f, dot));
            found = dist < c2;
        }
        if (found) tpc++;
    }
    ltc = __reduce_add_sync(0xFFFFFFFFu, ltc);
    tpc = __reduce_add_sync(0xFFFFFFFFu, tpc);
    if (lane == 0) {
        if (ltc) atomicAdd(&sLT, ltc);
        if (tpc) atomicAdd(&sTP, tpc);
    }
    __syncthreads();

    if (tid == 0) {
        int tp = sTP, lp = sLP, lt = sLT;
        out[prob * 3 + 0] = (float)tp;
        out[prob * 3 + 1] = (float)(lp - tp);
        out[prob * 3 + 2] = (float)(lt - tp);
    }
}

extern "C" void kernel_launch(void* const* d_in, const int* in_sizes, int n_in,
                              void* d_out, int out_size)
{
    const float* pred_clses = (const float*)d_in[0];
    const float* pred_boxes = (const float*)d_in[1];
    const int*   targ_clses = (const int*)d_in[2];
    const float* targ_boxes = (const float*)d_in[3];
    float* out = (float*)d_out;

    k_prep<<<NPROB, 1024>>>(pred_clses, pred_boxes);
    k_edges<<<dim3(64, NPROB), 256>>>();
    k_nms_match<<<NPROB, 1024>>>(targ_clses, targ_boxes, out);
}